// round 3
// baseline (speedup 1.0000x reference)
#include <cuda_runtime.h>
#include <math.h>

// Problem constants
#define N_   1024
#define B_   4
#define C_   1024
#define H_   16
#define HD_  64
#define M_   (N_*B_)            // 4096 rows for the big GEMMs
#define LOGIT_MAX 4.6051701859880914f  // log(100)

// Scratch (allocation-free rule: __device__ globals)
__device__ float g_q[M_*C_];
__device__ float g_k[M_*C_];
__device__ float g_v[M_*C_];
__device__ float g_x[M_*C_];

// ---------------------------------------------------------------------------
// GEMM: C[m][n] = sum_k A[m][k] * W[n][k] + bias[n]
// A: (M x K) row-major, W: (N x K) row-major (i.e. C = A @ W^T + b)
// Tiles: BM=128, BN=64, BK=16, 256 threads, 8x4 per thread.
// ---------------------------------------------------------------------------
__global__ __launch_bounds__(256) void gemm_nt_kernel(
    const float* __restrict__ A, const float* __restrict__ W,
    const float* __restrict__ bias, float* __restrict__ C,
    int M, int N, int K)
{
    const int BM = 128, BN = 64, BK = 16;
    __shared__ float As[BK][BM + 4];   // pad to cut store conflicts
    __shared__ float Ws[BK][BN + 4];

    const int tid = threadIdx.x;
    const int tx = tid & 15;          // 0..15 -> 4 cols each
    const int ty = tid >> 4;          // 0..15 -> 8 rows each
    const int m0 = blockIdx.y * BM;
    const int n0 = blockIdx.x * BN;

    float acc[8][4];
    #pragma unroll
    for (int i = 0; i < 8; i++)
        #pragma unroll
        for (int j = 0; j < 4; j++) acc[i][j] = 0.f;

    for (int k0 = 0; k0 < K; k0 += BK) {
        // Load A tile (128x16) as float4, store transposed
        #pragma unroll
        for (int u = 0; u < 2; u++) {
            int idx = tid + u * 256;          // 0..511
            int row = idx >> 2;               // 0..127
            int kq  = idx & 3;                // 0..3
            float4 va = *(const float4*)&A[(size_t)(m0 + row) * K + k0 + kq * 4];
            As[kq*4+0][row] = va.x; As[kq*4+1][row] = va.y;
            As[kq*4+2][row] = va.z; As[kq*4+3][row] = va.w;
        }
        // Load W tile (64x16)
        {
            int row = tid >> 2;               // 0..63
            int kq  = tid & 3;
            float4 vw = *(const float4*)&W[(size_t)(n0 + row) * K + k0 + kq * 4];
            Ws[kq*4+0][row] = vw.x; Ws[kq*4+1][row] = vw.y;
            Ws[kq*4+2][row] = vw.z; Ws[kq*4+3][row] = vw.w;
        }
        __syncthreads();

        #pragma unroll
        for (int kk = 0; kk < BK; kk++) {
            float4 a0 = *(float4*)&As[kk][ty * 8];
            float4 a1 = *(float4*)&As[kk][ty * 8 + 4];
            float4 bb = *(float4*)&Ws[kk][tx * 4];
            float ar[8] = {a0.x, a0.y, a0.z, a0.w, a1.x, a1.y, a1.z, a1.w};
            float br[4] = {bb.x, bb.y, bb.z, bb.w};
            #pragma unroll
            for (int i = 0; i < 8; i++)
                #pragma unroll
                for (int j = 0; j < 4; j++)
                    acc[i][j] += ar[i] * br[j];
        }
        __syncthreads();
    }

    // Epilogue: add bias, vectorized store
    int col = n0 + tx * 4;
    float4 b4 = *(const float4*)&bias[col];
    #pragma unroll
    for (int i = 0; i < 8; i++) {
        int row = m0 + ty * 8 + i;
        float4 o;
        o.x = acc[i][0] + b4.x; o.y = acc[i][1] + b4.y;
        o.z = acc[i][2] + b4.z; o.w = acc[i][3] + b4.w;
        *(float4*)&C[(size_t)row * N + col] = o;
    }
}

// ---------------------------------------------------------------------------
// Per-(row, head) L2 normalize; optionally fold exp(min(ls, LOGIT_MAX)) scale
// One warp per 64-element head vector.
// ---------------------------------------------------------------------------
__global__ __launch_bounds__(256) void norm_kernel(
    float* __restrict__ buf, const float* __restrict__ ls, int applyScale)
{
    int gw = (blockIdx.x * 256 + threadIdx.x) >> 5;   // global warp id
    int lane = threadIdx.x & 31;
    if (gw >= M_ * H_) return;
    int m = gw >> 4;     // row (n*B+b)
    int h = gw & 15;     // head
    float* p = buf + (size_t)m * C_ + h * HD_;
    float v0 = p[lane], v1 = p[lane + 32];
    float ss = v0 * v0 + v1 * v1;
    #pragma unroll
    for (int o = 16; o; o >>= 1) ss += __shfl_xor_sync(0xffffffffu, ss, o);
    float inv = rsqrtf(fmaxf(ss, 1e-24f));
    if (applyScale) inv *= __expf(fminf(ls[h], LOGIT_MAX));
    p[lane] = v0 * inv;
    p[lane + 32] = v1 * inv;
}

// ---------------------------------------------------------------------------
// Flash attention, fp32. Grid: (N/64, B*H). Block: 256 threads.
// q already carries the logit scale; q/k already normalized.
// Thread t: query row r = t/4, group g = t%4.
//  - S stage: thread computes scores for cols c = g + 4j (j=0..15)
//  - PV stage: thread accumulates O cols c = g*4 + 16*i (+0..3), i=0..3
// ---------------------------------------------------------------------------
#define QS 68   // Qs row stride (floats)
#define KS 72   // Ks/Vs row stride
#define PS 65   // Ps row stride

__global__ __launch_bounds__(256) void attn_kernel(
    const float* __restrict__ q, const float* __restrict__ k,
    const float* __restrict__ v, float* __restrict__ x)
{
    extern __shared__ float sm[];
    float* Qs = sm;                  // 64 x QS
    float* Ks = Qs + 64 * QS;        // 64 x KS
    float* Vs = Ks + 64 * KS;        // 64 x KS
    float* Ps = Vs + 64 * KS;        // 64 x PS

    const int tid = threadIdx.x;
    const int r = tid >> 2;          // query row in tile
    const int g = tid & 3;
    const int qt = blockIdx.x;       // query tile 0..15
    const int bh = blockIdx.y;       // 0..63
    const int b = bh >> 4, h = bh & 15;
    const int n0 = qt * 64;
    const size_t rs = (size_t)B_ * C_;          // stride between tokens
    const size_t hb = (size_t)b * C_ + h * HD_; // (b, h) offset

    const float* qbase = q + hb;
    const float* kbase = k + hb;
    const float* vbase = v + hb;

    // Load Q tile (64 x 64)
    for (int idx = tid; idx < 64 * 16; idx += 256) {
        int row = idx >> 4, d4 = idx & 15;
        *(float4*)&Qs[row * QS + d4 * 4] =
            *(const float4*)&qbase[(size_t)(n0 + row) * rs + d4 * 4];
    }

    float4 o0 = {0,0,0,0}, o1 = {0,0,0,0}, o2 = {0,0,0,0}, o3 = {0,0,0,0};
    float mrow = -1e30f, lrow = 0.f;

    for (int kt = 0; kt < 16; kt++) {
        __syncthreads();   // previous PV/loads finished before overwrite
        int kn0 = kt * 64;
        for (int idx = tid; idx < 64 * 16; idx += 256) {
            int row = idx >> 4, d4 = idx & 15;
            size_t go = (size_t)(kn0 + row) * rs + d4 * 4;
            *(float4*)&Ks[row * KS + d4 * 4] = *(const float4*)&kbase[go];
            *(float4*)&Vs[row * KS + d4 * 4] = *(const float4*)&vbase[go];
        }
        __syncthreads();

        // --- scores for cols c = g + 4j ---
        float s[16];
        #pragma unroll
        for (int j = 0; j < 16; j++) s[j] = 0.f;
        #pragma unroll
        for (int d4 = 0; d4 < 16; d4++) {
            float4 q4 = *(float4*)&Qs[r * QS + d4 * 4];
            #pragma unroll
            for (int j = 0; j < 16; j++) {
                float4 k4 = *(float4*)&Ks[(g + 4 * j) * KS + d4 * 4];
                s[j] += q4.x * k4.x + q4.y * k4.y + q4.z * k4.z + q4.w * k4.w;
            }
        }

        // --- online softmax ---
        float tmax = s[0];
        #pragma unroll
        for (int j = 1; j < 16; j++) tmax = fmaxf(tmax, s[j]);
        tmax = fmaxf(tmax, __shfl_xor_sync(0xffffffffu, tmax, 1));
        tmax = fmaxf(tmax, __shfl_xor_sync(0xffffffffu, tmax, 2));
        float mnew = fmaxf(mrow, tmax);
        float corr = __expf(mrow - mnew);
        lrow *= corr;
        o0.x *= corr; o0.y *= corr; o0.z *= corr; o0.w *= corr;
        o1.x *= corr; o1.y *= corr; o1.z *= corr; o1.w *= corr;
        o2.x *= corr; o2.y *= corr; o2.z *= corr; o2.w *= corr;
        o3.x *= corr; o3.y *= corr; o3.z *= corr; o3.w *= corr;

        float psum = 0.f;
        #pragma unroll
        for (int j = 0; j < 16; j++) {
            float pv = __expf(s[j] - mnew);
            psum += pv;
            Ps[r * PS + g + 4 * j] = pv;
        }
        psum += __shfl_xor_sync(0xffffffffu, psum, 1);
        psum += __shfl_xor_sync(0xffffffffu, psum, 2);
        lrow += psum;
        mrow = mnew;
        __syncwarp();   // P row visible within the 4-thread group's warp

        // --- O += P @ V (thread cols: g*4 + 16*i) ---
        #pragma unroll
        for (int j = 0; j < 64; j++) {
            float pv = Ps[r * PS + j];
            const float* vr = &Vs[j * KS + g * 4];
            float4 v0 = *(const float4*)&vr[0];
            float4 v1 = *(const float4*)&vr[16];
            float4 v2 = *(const float4*)&vr[32];
            float4 v3 = *(const float4*)&vr[48];
            o0.x += pv * v0.x; o0.y += pv * v0.y; o0.z += pv * v0.z; o0.w += pv * v0.w;
            o1.x += pv * v1.x; o1.y += pv * v1.y; o1.z += pv * v1.z; o1.w += pv * v1.w;
            o2.x += pv * v2.x; o2.y += pv * v2.y; o2.z += pv * v2.z; o2.w += pv * v2.w;
            o3.x += pv * v3.x; o3.y += pv * v3.y; o3.z += pv * v3.z; o3.w += pv * v3.w;
        }
        __syncwarp();   // P reads done before next tile rewrites it
    }

    // Epilogue: normalize by l, write to x in (M, C) layout
    float invl = 1.f / lrow;
    float* xb = x + hb + (size_t)(n0 + r) * rs + g * 4;
    float4 w0 = {o0.x*invl, o0.y*invl, o0.z*invl, o0.w*invl};
    float4 w1 = {o1.x*invl, o1.y*invl, o1.z*invl, o1.w*invl};
    float4 w2 = {o2.x*invl, o2.y*invl, o2.z*invl, o2.w*invl};
    float4 w3 = {o3.x*invl, o3.y*invl, o3.z*invl, o3.w*invl};
    *(float4*)&xb[0]  = w0;
    *(float4*)&xb[16] = w1;
    *(float4*)&xb[32] = w2;
    *(float4*)&xb[48] = w3;
}

// ---------------------------------------------------------------------------
// Launcher
// ---------------------------------------------------------------------------
extern "C" void kernel_launch(void* const* d_in, const int* in_sizes, int n_in,
                              void* d_out, int out_size)
{
    const float* query = (const float*)d_in[0];
    const float* key   = (const float*)d_in[1];
    const float* value = (const float*)d_in[2];
    const float* ipw   = (const float*)d_in[3];   // (3C, C)
    const float* ipb   = (const float*)d_in[4];   // (3C)
    const float* ls    = (const float*)d_in[5];   // (H,1,1)
    const float* outw  = (const float*)d_in[6];   // (C, C)
    const float* outb  = (const float*)d_in[7];   // (C)
    float* out = (float*)d_out;

    float *q, *k, *v, *x;
    cudaGetSymbolAddress((void**)&q, g_q);
    cudaGetSymbolAddress((void**)&k, g_k);
    cudaGetSymbolAddress((void**)&v, g_v);
    cudaGetSymbolAddress((void**)&x, g_x);

    dim3 gg(C_ / 64, M_ / 128);   // (16, 32)

    // In-projections: q/k/v = inp @ W^T + b
    gemm_nt_kernel<<<gg, 256>>>(query, ipw,               ipb,        q, M_, C_, C_);
    gemm_nt_kernel<<<gg, 256>>>(key,   ipw + (size_t)C_*C_,   ipb + C_,   k, M_, C_, C_);
    gemm_nt_kernel<<<gg, 256>>>(value, ipw + (size_t)2*C_*C_, ipb + 2*C_, v, M_, C_, C_);

    // L2-normalize heads; fold logit scale into q
    norm_kernel<<<(M_ * H_) / 8, 256>>>(q, ls, 1);
    norm_kernel<<<(M_ * H_) / 8, 256>>>(k, ls, 0);

    // Flash attention
    const int smem = (64 * QS + 64 * KS + 64 * KS + 64 * PS) * (int)sizeof(float);
    cudaFuncSetAttribute(attn_kernel, cudaFuncAttributeMaxDynamicSharedMemorySize, smem);
    attn_kernel<<<dim3(N_ / 64, B_ * H_), 256, smem>>>(q, k, v, x);

    // Output projection
    gemm_nt_kernel<<<gg, 256>>>(x, outw, outb, out, M_, C_, C_);
}

// round 5
// speedup vs baseline: 1.4568x; 1.4568x over previous
#include <cuda_runtime.h>
#include <math.h>
#include <stdint.h>

// Problem constants
#define N_   1024
#define B_   4
#define C_   1024
#define H_   16
#define HD_  64
#define M_   (N_*B_)            // 4096 rows for the big GEMMs
#define LOGIT_MAX 4.6051701859880914f  // log(100)

// Scratch (allocation-free rule: __device__ globals)
__device__ float g_q[M_*C_];
__device__ float g_k[M_*C_];
__device__ float g_v[M_*C_];
__device__ float g_x[M_*C_];

// ===========================================================================
// TF32 tensor-core GEMM: C[m][n] = sum_k A[m][k] * W[n][k] + bias[n]
// A: (M x K) row-major, W: (N x K) row-major  (C = A @ W^T + b)
// Block tile 128x128, BK=32, 256 threads (8 warps, 2x4), warp tile 64x32.
// mma.sync.aligned.m16n8k8.row.col.f32.tf32.tf32.f32
// Inputs converted with cvt.rna.tf32.f32 at the smem-store stage (unbiased).
// ===========================================================================
#define GBM 128
#define GBN 128
#define GBK 32
#define ASTRIDE 36            // padded smem row stride (floats): conflict-free frags
#define SLAB (128*ASTRIDE)    // 4608 floats per operand slab
#define BUFSZ (2*SLAB)        // A+B per buffer

__device__ __forceinline__ uint32_t f2tf(float x) {
    uint32_t u;
    asm("cvt.rna.tf32.f32 %0, %1;" : "=r"(u) : "f"(x));
    return u;
}

__device__ __forceinline__ void mma_tf32(float* c, const uint32_t* a, const uint32_t* b) {
    asm volatile(
        "mma.sync.aligned.m16n8k8.row.col.f32.tf32.tf32.f32 "
        "{%0,%1,%2,%3}, {%4,%5,%6,%7}, {%8,%9}, {%0,%1,%2,%3};"
        : "+f"(c[0]), "+f"(c[1]), "+f"(c[2]), "+f"(c[3])
        : "r"(a[0]), "r"(a[1]), "r"(a[2]), "r"(a[3]), "r"(b[0]), "r"(b[1]));
}

__device__ __forceinline__ void ldg_tile(
    const float* __restrict__ A, const float* __restrict__ W,
    int m0, int n0, int K, int k0, int tid, float4* ra, float4* rb)
{
    #pragma unroll
    for (int u = 0; u < 4; u++) {
        int lin = tid + u * 256;
        int row = lin >> 3, kq = lin & 7;
        ra[u] = *(const float4*)&A[(size_t)(m0 + row) * K + k0 + kq * 4];
        rb[u] = *(const float4*)&W[(size_t)(n0 + row) * K + k0 + kq * 4];
    }
}

__device__ __forceinline__ void cvt_sts_tile(
    float* Ab, float* Bb, const float4* ra, const float4* rb, int tid)
{
    #pragma unroll
    for (int u = 0; u < 4; u++) {
        int lin = tid + u * 256;
        int row = lin >> 3, kq = lin & 7;
        float4 va, vb;
        va.x = __uint_as_float(f2tf(ra[u].x));
        va.y = __uint_as_float(f2tf(ra[u].y));
        va.z = __uint_as_float(f2tf(ra[u].z));
        va.w = __uint_as_float(f2tf(ra[u].w));
        vb.x = __uint_as_float(f2tf(rb[u].x));
        vb.y = __uint_as_float(f2tf(rb[u].y));
        vb.z = __uint_as_float(f2tf(rb[u].z));
        vb.w = __uint_as_float(f2tf(rb[u].w));
        *(float4*)(Ab + row * ASTRIDE + kq * 4) = va;   // stride 144B = 9*16B, aligned
        *(float4*)(Bb + row * ASTRIDE + kq * 4) = vb;
    }
}

__global__ __launch_bounds__(256) void gemm_tf32_kernel(
    const float* __restrict__ A, const float* __restrict__ W,
    const float* __restrict__ bias, float* __restrict__ C,
    int M, int N, int K)
{
    extern __shared__ float smem[];
    const int tid  = threadIdx.x;
    const int warp = tid >> 5, lane = tid & 31;
    const int wm = warp >> 2, wn = warp & 3;     // 2 x 4 warp grid
    const int lr = lane >> 2, lc = lane & 3;
    const int m0 = blockIdx.y * GBM, n0 = blockIdx.x * GBN;

    float acc[4][4][4];
    #pragma unroll
    for (int i = 0; i < 4; i++)
        #pragma unroll
        for (int j = 0; j < 4; j++)
            #pragma unroll
            for (int r = 0; r < 4; r++) acc[i][j][r] = 0.f;

    float4 ra[4], rb[4];

    // Prologue: tile 0 -> buffer 0
    ldg_tile(A, W, m0, n0, K, 0, tid, ra, rb);
    cvt_sts_tile(smem, smem + SLAB, ra, rb, tid);
    __syncthreads();

    const int NT = K / GBK;   // 32
    for (int t = 0; t < NT; t++) {
        const int buf = t & 1;
        if (t + 1 < NT)
            ldg_tile(A, W, m0, n0, K, (t + 1) * GBK, tid, ra, rb);

        float* Ab = smem + buf * BUFSZ;
        float* Bb = Ab + SLAB;

        #pragma unroll
        for (int ks = 0; ks < 4; ks++) {
            uint32_t af[4][4];
            uint32_t bf[4][2];
            #pragma unroll
            for (int mt = 0; mt < 4; mt++) {
                const float* p = Ab + (wm * 64 + mt * 16 + lr) * ASTRIDE + ks * 8 + lc;
                af[mt][0] = __float_as_uint(p[0]);
                af[mt][1] = __float_as_uint(p[8 * ASTRIDE]);
                af[mt][2] = __float_as_uint(p[4]);
                af[mt][3] = __float_as_uint(p[8 * ASTRIDE + 4]);
            }
            #pragma unroll
            for (int nt = 0; nt < 4; nt++) {
                const float* p = Bb + (wn * 32 + nt * 8 + lr) * ASTRIDE + ks * 8 + lc;
                bf[nt][0] = __float_as_uint(p[0]);
                bf[nt][1] = __float_as_uint(p[4]);
            }
            #pragma unroll
            for (int mt = 0; mt < 4; mt++)
                #pragma unroll
                for (int nt = 0; nt < 4; nt++)
                    mma_tf32(acc[mt][nt], af[mt], bf[nt]);
        }

        if (t + 1 < NT)
            cvt_sts_tile(smem + (buf ^ 1) * BUFSZ, smem + (buf ^ 1) * BUFSZ + SLAB,
                         ra, rb, tid);
        __syncthreads();
    }

    // Epilogue: bias add, float2 stores
    #pragma unroll
    for (int mt = 0; mt < 4; mt++) {
        const int row = m0 + wm * 64 + mt * 16 + lr;
        #pragma unroll
        for (int nt = 0; nt < 4; nt++) {
            const int col = n0 + wn * 32 + nt * 8 + 2 * lc;
            const float bx = bias[col], by = bias[col + 1];
            float2 o0 = { acc[mt][nt][0] + bx, acc[mt][nt][1] + by };
            float2 o1 = { acc[mt][nt][2] + bx, acc[mt][nt][3] + by };
            *(float2*)&C[(size_t)row * N + col]       = o0;
            *(float2*)&C[(size_t)(row + 8) * N + col] = o1;
        }
    }
}

// ---------------------------------------------------------------------------
// Per-(row, head) L2 normalize; optionally fold exp(min(ls, LOGIT_MAX)) scale
// ---------------------------------------------------------------------------
__global__ __launch_bounds__(256) void norm_kernel(
    float* __restrict__ buf, const float* __restrict__ ls, int applyScale)
{
    int gw = (blockIdx.x * 256 + threadIdx.x) >> 5;   // global warp id
    int lane = threadIdx.x & 31;
    if (gw >= M_ * H_) return;
    int m = gw >> 4;     // row (n*B+b)
    int h = gw & 15;     // head
    float* p = buf + (size_t)m * C_ + h * HD_;
    float v0 = p[lane], v1 = p[lane + 32];
    float ss = v0 * v0 + v1 * v1;
    #pragma unroll
    for (int o = 16; o; o >>= 1) ss += __shfl_xor_sync(0xffffffffu, ss, o);
    float inv = rsqrtf(fmaxf(ss, 1e-24f));
    if (applyScale) inv *= __expf(fminf(ls[h], LOGIT_MAX));
    p[lane] = v0 * inv;
    p[lane + 32] = v1 * inv;
}

// ---------------------------------------------------------------------------
// Flash attention, fp32. Grid: (N/64, B*H). Block: 256 threads.
// ---------------------------------------------------------------------------
#define QS 68   // Qs row stride (floats)
#define KS 72   // Ks/Vs row stride
#define PS 65   // Ps row stride

__global__ __launch_bounds__(256) void attn_kernel(
    const float* __restrict__ q, const float* __restrict__ k,
    const float* __restrict__ v, float* __restrict__ x)
{
    extern __shared__ float sm[];
    float* Qs = sm;                  // 64 x QS
    float* Ks = Qs + 64 * QS;        // 64 x KS
    float* Vs = Ks + 64 * KS;        // 64 x KS
    float* Ps = Vs + 64 * KS;        // 64 x PS

    const int tid = threadIdx.x;
    const int r = tid >> 2;          // query row in tile
    const int g = tid & 3;
    const int qt = blockIdx.x;       // query tile 0..15
    const int bh = blockIdx.y;       // 0..63
    const int b = bh >> 4, h = bh & 15;
    const int n0 = qt * 64;
    const size_t rs = (size_t)B_ * C_;          // stride between tokens
    const size_t hb = (size_t)b * C_ + h * HD_; // (b, h) offset

    const float* qbase = q + hb;
    const float* kbase = k + hb;
    const float* vbase = v + hb;

    // Load Q tile (64 x 64)
    for (int idx = tid; idx < 64 * 16; idx += 256) {
        int row = idx >> 4, d4 = idx & 15;
        *(float4*)&Qs[row * QS + d4 * 4] =
            *(const float4*)&qbase[(size_t)(n0 + row) * rs + d4 * 4];
    }

    float4 o0 = {0,0,0,0}, o1 = {0,0,0,0}, o2 = {0,0,0,0}, o3 = {0,0,0,0};
    float mrow = -1e30f, lrow = 0.f;

    for (int kt = 0; kt < 16; kt++) {
        __syncthreads();   // previous PV/loads finished before overwrite
        int kn0 = kt * 64;
        for (int idx = tid; idx < 64 * 16; idx += 256) {
            int row = idx >> 4, d4 = idx & 15;
            size_t go = (size_t)(kn0 + row) * rs + d4 * 4;
            *(float4*)&Ks[row * KS + d4 * 4] = *(const float4*)&kbase[go];
            *(float4*)&Vs[row * KS + d4 * 4] = *(const float4*)&vbase[go];
        }
        __syncthreads();

        // --- scores for cols c = g + 4j ---
        float s[16];
        #pragma unroll
        for (int j = 0; j < 16; j++) s[j] = 0.f;
        #pragma unroll
        for (int d4 = 0; d4 < 16; d4++) {
            float4 q4 = *(float4*)&Qs[r * QS + d4 * 4];
            #pragma unroll
            for (int j = 0; j < 16; j++) {
                float4 k4 = *(float4*)&Ks[(g + 4 * j) * KS + d4 * 4];
                s[j] += q4.x * k4.x + q4.y * k4.y + q4.z * k4.z + q4.w * k4.w;
            }
        }

        // --- online softmax ---
        float tmax = s[0];
        #pragma unroll
        for (int j = 1; j < 16; j++) tmax = fmaxf(tmax, s[j]);
        tmax = fmaxf(tmax, __shfl_xor_sync(0xffffffffu, tmax, 1));
        tmax = fmaxf(tmax, __shfl_xor_sync(0xffffffffu, tmax, 2));
        float mnew = fmaxf(mrow, tmax);
        float corr = __expf(mrow - mnew);
        lrow *= corr;
        o0.x *= corr; o0.y *= corr; o0.z *= corr; o0.w *= corr;
        o1.x *= corr; o1.y *= corr; o1.z *= corr; o1.w *= corr;
        o2.x *= corr; o2.y *= corr; o2.z *= corr; o2.w *= corr;
        o3.x *= corr; o3.y *= corr; o3.z *= corr; o3.w *= corr;

        float psum = 0.f;
        #pragma unroll
        for (int j = 0; j < 16; j++) {
            float pv = __expf(s[j] - mnew);
            psum += pv;
            Ps[r * PS + g + 4 * j] = pv;
        }
        psum += __shfl_xor_sync(0xffffffffu, psum, 1);
        psum += __shfl_xor_sync(0xffffffffu, psum, 2);
        lrow += psum;
        mrow = mnew;
        __syncwarp();   // P row visible within the 4-thread group's warp

        // --- O += P @ V (thread cols: g*4 + 16*i) ---
        #pragma unroll
        for (int j = 0; j < 64; j++) {
            float pv = Ps[r * PS + j];
            const float* vr = &Vs[j * KS + g * 4];
            float4 v0 = *(const float4*)&vr[0];
            float4 v1 = *(const float4*)&vr[16];
            float4 v2 = *(const float4*)&vr[32];
            float4 v3 = *(const float4*)&vr[48];
            o0.x += pv * v0.x; o0.y += pv * v0.y; o0.z += pv * v0.z; o0.w += pv * v0.w;
            o1.x += pv * v1.x; o1.y += pv * v1.y; o1.z += pv * v1.z; o1.w += pv * v1.w;
            o2.x += pv * v2.x; o2.y += pv * v2.y; o2.z += pv * v2.z; o2.w += pv * v2.w;
            o3.x += pv * v3.x; o3.y += pv * v3.y; o3.z += pv * v3.z; o3.w += pv * v3.w;
        }
        __syncwarp();   // P reads done before next tile rewrites it
    }

    // Epilogue: normalize by l, write to x in (M, C) layout
    float invl = 1.f / lrow;
    float* xb = x + hb + (size_t)(n0 + r) * rs + g * 4;
    float4 w0 = {o0.x*invl, o0.y*invl, o0.z*invl, o0.w*invl};
    float4 w1 = {o1.x*invl, o1.y*invl, o1.z*invl, o1.w*invl};
    float4 w2 = {o2.x*invl, o2.y*invl, o2.z*invl, o2.w*invl};
    float4 w3 = {o3.x*invl, o3.y*invl, o3.z*invl, o3.w*invl};
    *(float4*)&xb[0]  = w0;
    *(float4*)&xb[16] = w1;
    *(float4*)&xb[32] = w2;
    *(float4*)&xb[48] = w3;
}

// ---------------------------------------------------------------------------
// Launcher
// ---------------------------------------------------------------------------
extern "C" void kernel_launch(void* const* d_in, const int* in_sizes, int n_in,
                              void* d_out, int out_size)
{
    const float* query = (const float*)d_in[0];
    const float* key   = (const float*)d_in[1];
    const float* value = (const float*)d_in[2];
    const float* ipw   = (const float*)d_in[3];   // (3C, C)
    const float* ipb   = (const float*)d_in[4];   // (3C)
    const float* ls    = (const float*)d_in[5];   // (H,1,1)
    const float* outw  = (const float*)d_in[6];   // (C, C)
    const float* outb  = (const float*)d_in[7];   // (C)
    float* out = (float*)d_out;

    float *q, *k, *v, *x;
    cudaGetSymbolAddress((void**)&q, g_q);
    cudaGetSymbolAddress((void**)&k, g_k);
    cudaGetSymbolAddress((void**)&v, g_v);
    cudaGetSymbolAddress((void**)&x, g_x);

    // TF32 GEMM setup
    dim3 gg(C_ / GBN, M_ / GBM);   // (8, 32)
    const int gsmem = 2 * BUFSZ * (int)sizeof(float);   // 73728 B
    static int gemm_attr_set = 0;
    if (!gemm_attr_set) {
        cudaFuncSetAttribute(gemm_tf32_kernel,
                             cudaFuncAttributeMaxDynamicSharedMemorySize, gsmem);
        gemm_attr_set = 1;
    }

    // In-projections: q/k/v = inp @ W^T + b
    gemm_tf32_kernel<<<gg, 256, gsmem>>>(query, ipw,                  ipb,          q, M_, C_, C_);
    gemm_tf32_kernel<<<gg, 256, gsmem>>>(key,   ipw + (size_t)C_*C_,  ipb + C_,     k, M_, C_, C_);
    gemm_tf32_kernel<<<gg, 256, gsmem>>>(value, ipw + (size_t)2*C_*C_, ipb + 2*C_,  v, M_, C_, C_);

    // L2-normalize heads; fold logit scale into q
    norm_kernel<<<(M_ * H_) / 8, 256>>>(q, ls, 1);
    norm_kernel<<<(M_ * H_) / 8, 256>>>(k, ls, 0);

    // Flash attention (fp32)
    const int smem = (64 * QS + 64 * KS + 64 * KS + 64 * PS) * (int)sizeof(float);
    static int attn_attr_set = 0;
    if (!attn_attr_set) {
        cudaFuncSetAttribute(attn_kernel,
                             cudaFuncAttributeMaxDynamicSharedMemorySize, smem);
        attn_attr_set = 1;
    }
    attn_kernel<<<dim3(N_ / 64, B_ * H_), 256, smem>>>(q, k, v, x);

    // Output projection
    gemm_tf32_kernel<<<gg, 256, gsmem>>>(x, outw, outb, out, M_, C_, C_);
}